// round 15
// baseline (speedup 1.0000x reference)
#include <cuda_runtime.h>
#include <cuda_bf16.h>
#include <math_constants.h>

// RWKV WKV scan. B=8, S=2048, H=2048.
// R12: single-pass decoupled lookback, CC=32 via CLEN=64 / GCH=128 / 1 ch per
// thread. Both k and v stay in the 64KB SMEM tile (3 blocks/SM). Chunk-boundary
// overhead (scratch traffic + lookback events) halves vs R8 without R9's
// v-from-L2 penalty. __ldcs on k/v (evict-first), __stcs on out (streaming).
// k,v cross DRAM exactly once; phase-3 replay from SMEM.

#define S_   2048
#define H_   2048
#define B_   8
#define BH_  (B_ * H_)        // 16384 channels
#define CLEN 64               // steps per chunk
#define CC   (S_ / CLEN)      // 32 chunks
#define GCH  128              // channels per group
#define GROUPS (BH_ / GCH)    // 128
#define NT   128              // threads per block (1 channel each)
#define PF   8                // prefetch ring depth (rows)

#define L2E 1.4426950408889634f

__device__ float g_aggm[GROUPS * CC * NT];
__device__ float g_aggn[GROUPS * CC * NT];
__device__ float g_aggd[GROUPS * CC * NT];
__device__ float g_incm[GROUPS * CC * NT];
__device__ float g_incn[GROUPS * CC * NT];
__device__ float g_incd[GROUPS * CC * NT];
__device__ int   g_status[GROUPS * CC];   // 0=none, 1=aggregate, 2=inclusive

__device__ __forceinline__ float ex2(float x) {
    float r;
    asm("ex2.approx.ftz.f32 %0, %1;" : "=f"(r) : "f"(x));
    return r;
}
__device__ __forceinline__ int ld_acquire(const int* p) {
    int v;
    asm volatile("ld.acquire.gpu.global.b32 %0, [%1];" : "=r"(v) : "l"(p));
    return v;
}
__device__ __forceinline__ void st_release(int* p, int v) {
    asm volatile("st.release.gpu.global.b32 [%0], %1;" :: "l"(p), "r"(v) : "memory");
}

__global__ void wkv_reset() {
    const int i = blockIdx.x * blockDim.x + threadIdx.x;
    if (i < GROUPS * CC) g_status[i] = 0;
}

__global__ void __launch_bounds__(NT, 3) wkv_main(
    const float* __restrict__ time_decay,
    const float* __restrict__ k,
    const float* __restrict__ time_first,
    const float* __restrict__ v,
    const float* __restrict__ m0,
    const float* __restrict__ n0,
    const float* __restrict__ d0,
    float* __restrict__ out)
{
    extern __shared__ float sh[];
    float* ks = sh;              // [CLEN][NT], k pre-scaled by L2E
    float* vs = sh + CLEN * NT;  // [CLEN][NT]
    __shared__ int s_st;

    const int tid = threadIdx.x;
    const int g   = blockIdx.x & (GROUPS - 1);
    const int c   = blockIdx.x >> 7;           // GROUPS = 128
    const int ch  = g * GCH + tid;             // one channel per thread
    const int h   = ch & (H_ - 1);
    const int b   = ch >> 11;

    const float td = -__expf(time_decay[h]) * L2E;

    const size_t base =
        (size_t)b * S_ * H_ + (size_t)c * CLEN * H_ + (size_t)h;
    const float* __restrict__ kp = k + base;
    const float* __restrict__ vp = v + base;

    // ---------------- Phase 1: load tile + local scan from identity ----------
    float am = -CUDART_INF_F, an = 0.f, ad = 0.f;

    float kb[PF], vb[PF];
#pragma unroll
    for (int r = 0; r < PF; ++r) {
        kb[r] = __ldcs(kp + (size_t)r * H_);
        vb[r] = __ldcs(vp + (size_t)r * H_);
    }

#pragma unroll 8
    for (int r = 0; r < CLEN; ++r) {
        const int slot = r & (PF - 1);
        const float kt = kb[slot] * L2E;
        const float vt = vb[slot];
        if (r + PF < CLEN) {
            kb[slot] = __ldcs(kp + (size_t)(r + PF) * H_);
            vb[slot] = __ldcs(vp + (size_t)(r + PF) * H_);
        }
        ks[r * NT + tid] = kt;
        vs[r * NT + tid] = vt;
        const float a  = am + td;
        const float d2 = a - kt;
        const float es = ex2(-fabsf(d2));
        const float e1 = (d2 >= 0.f) ? 1.f : es;
        const float e2 = (d2 >= 0.f) ? es : 1.f;
        am = fmaxf(a, kt);
        an = fmaf(e1, an, e2 * vt);
        ad = fmaf(e1, ad, e2);
    }

    // ---------------- Phase 2: publish + lookback -> entry state -------------
    const int gi = g * CC + c;
    const int qi = gi * NT + tid;
    float exm, exn, exd;

    if (c == 0) {
        exm = m0[ch] * L2E;
        exn = n0[ch];
        exd = d0[ch];
    } else {
        g_aggm[qi] = am;
        g_aggn[qi] = an;
        g_aggd[qi] = ad;
        __syncthreads();
        if (tid == 0) st_release(&g_status[gi], 1);

        float sm = -CUDART_INF_F, sn = 0.f, sd = 0.f;
        float slen = 0.f;
        int idx = gi - 1;

        for (;;) {
            if (tid == 0) {
                int s;
                while ((s = ld_acquire(&g_status[idx])) == 0) __nanosleep(40);
                s_st = s;
            }
            __syncthreads();
            const int s = s_st;
            __syncthreads();
            const int q2 = idx * NT + tid;
            if (s == 1) {
                const float Am = g_aggm[q2];
                const float An = g_aggn[q2];
                const float Ad = g_aggd[q2];
                const float a  = fmaf(slen, td, Am);
                const float mo = fmaxf(a, sm);
                const float e1 = ex2(a - mo);
                const float e2 = ex2(sm - mo);
                sn = fmaf(e1, An, e2 * sn);
                sd = fmaf(e1, Ad, e2 * sd);
                sm = mo;
                slen += (float)CLEN;
                --idx;
            } else {
                const float Em = g_incm[q2];
                const float En = g_incn[q2];
                const float Ed = g_incd[q2];
                const float a  = fmaf(slen, td, Em);
                const float mo = fmaxf(a, sm);
                const float e1 = ex2(a - mo);
                const float e2 = ex2(sm - mo);
                exn = fmaf(e1, En, e2 * sn);
                exd = fmaf(e1, Ed, e2 * sd);
                exm = mo;
                break;
            }
        }
    }

    // inclusive(c) = compose(exclusive, own aggregate over CLEN steps)
    if (c < CC - 1) {
        const float a  = fmaf((float)CLEN, td, exm);
        const float mo = fmaxf(a, am);
        const float e1 = ex2(a - mo);
        const float e2 = ex2(am - mo);
        g_incn[qi] = fmaf(e1, exn, e2 * an);
        g_incd[qi] = fmaf(e1, exd, e2 * ad);
        g_incm[qi] = mo;
        __syncthreads();
        if (tid == 0) st_release(&g_status[gi], 2);
    }

    // ---------------- Phase 3: outputs from exact entry state (SMEM replay) --
    const float tf = time_first[h] * L2E;

    float m = exm, num = exn, den = exd;

    float* __restrict__ op = out + base;

#pragma unroll 8
    for (int r = 0; r < CLEN; ++r) {
        const float kt = ks[r * NT + tid];   // pre-scaled by L2E
        const float vt = vs[r * NT + tid];

        // output branch
        const float btf = kt + tf;
        const float d1  = m - btf;
        const float eo  = ex2(-fabsf(d1));
        const float e1o = (d1 >= 0.f) ? 1.f : eo;
        const float e2o = (d1 >= 0.f) ? eo : 1.f;
        const float on  = fmaf(e1o, num, e2o * vt);
        const float od  = fmaf(e1o, den, e2o);
        __stcs(op + (size_t)r * H_, __fdividef(on, od));

        // state branch
        const float a  = m + td;
        const float d2 = a - kt;
        const float es = ex2(-fabsf(d2));
        const float e1 = (d2 >= 0.f) ? 1.f : es;
        const float e2 = (d2 >= 0.f) ? es : 1.f;
        m   = fmaxf(a, kt);
        num = fmaf(e1, num, e2 * vt);
        den = fmaf(e1, den, e2);
    }

    if (c == CC - 1) {
        float* st = out + (size_t)B_ * S_ * H_;
        st[ch]           = m * (1.f / L2E);
        st[BH_ + ch]     = num;
        st[2 * BH_ + ch] = den;
    }
}

extern "C" void kernel_launch(void* const* d_in, const int* in_sizes, int n_in,
                              void* d_out, int out_size) {
    const float* time_decay = (const float*)d_in[0];
    const float* key        = (const float*)d_in[1];
    const float* time_first = (const float*)d_in[2];
    const float* value      = (const float*)d_in[3];
    const float* max_state  = (const float*)d_in[4];
    const float* num_state  = (const float*)d_in[5];
    const float* den_state  = (const float*)d_in[6];
    float* out = (float*)d_out;

    const int smem = 2 * CLEN * NT * sizeof(float);   // 64 KB
    cudaFuncSetAttribute(wkv_main, cudaFuncAttributeMaxDynamicSharedMemorySize, smem);

    wkv_reset<<<(GROUPS * CC + 255) / 256, 256>>>();
    wkv_main<<<GROUPS * CC, NT, smem>>>(time_decay, key, time_first, value,
                                        max_state, num_state, den_state, out);
}

// round 16
// speedup vs baseline: 1.3581x; 1.3581x over previous
#include <cuda_runtime.h>
#include <cuda_bf16.h>
#include <math_constants.h>

// RWKV WKV scan. B=8, S=2048, H=2048.
// R13 = R8 (best: 88.6us) + consolidation trims:
//  (1) reset kernel replaced by cudaMemsetAsync graph node on g_status
//  (2) __ldcs on phase-1 k/v (evict-first), __stcs on phase-3 out (streaming)
//  (3) double-buffered status broadcast: one __syncthreads per lookback iter
// Structure: single-pass decoupled lookback, CLEN=32, CC=64, GCH=256,
// 2 ch/thread (float2), 64KB k/v tile -> 3 blocks/SM. k,v cross DRAM once.

#define S_   2048
#define H_   2048
#define B_   8
#define BH_  (B_ * H_)        // 16384 channels
#define CLEN 32               // steps per chunk
#define CC   (S_ / CLEN)      // 64 chunks
#define GCH  256              // channels per group
#define GROUPS (BH_ / GCH)    // 64
#define NT   128              // threads per block (2 channels each)
#define ROW2 (H_ / 2)         // 1024 float2 per row
#define PF   8                // prefetch ring depth (rows)

#define L2E 1.4426950408889634f

__device__ float2 g_aggm[GROUPS * CC * NT];
__device__ float2 g_aggn[GROUPS * CC * NT];
__device__ float2 g_aggd[GROUPS * CC * NT];
__device__ float2 g_incm[GROUPS * CC * NT];
__device__ float2 g_incn[GROUPS * CC * NT];
__device__ float2 g_incd[GROUPS * CC * NT];
__device__ int    g_status[GROUPS * CC];   // 0=none, 1=aggregate, 2=inclusive

__device__ __forceinline__ float ex2(float x) {
    float r;
    asm("ex2.approx.ftz.f32 %0, %1;" : "=f"(r) : "f"(x));
    return r;
}
__device__ __forceinline__ int ld_acquire(const int* p) {
    int v;
    asm volatile("ld.acquire.gpu.global.b32 %0, [%1];" : "=r"(v) : "l"(p));
    return v;
}
__device__ __forceinline__ void st_release(int* p, int v) {
    asm volatile("st.release.gpu.global.b32 [%0], %1;" :: "l"(p), "r"(v) : "memory");
}

__global__ void __launch_bounds__(NT, 3) wkv_main(
    const float* __restrict__ time_decay,
    const float* __restrict__ k,
    const float* __restrict__ time_first,
    const float* __restrict__ v,
    const float* __restrict__ m0,
    const float* __restrict__ n0,
    const float* __restrict__ d0,
    float* __restrict__ out)
{
    extern __shared__ float2 sh[];
    float2* ks = sh;                 // [CLEN][NT], k pre-scaled by L2E
    float2* vs = sh + CLEN * NT;     // [CLEN][NT]
    __shared__ int s_st[2];          // double-buffered status broadcast

    const int tid = threadIdx.x;
    const int g   = blockIdx.x & (GROUPS - 1);
    const int c   = blockIdx.x >> 6;           // GROUPS = 64
    const int ch0 = g * GCH + 2 * tid;
    const int h0  = ch0 & (H_ - 1);
    const int b   = ch0 >> 11;

    const float2 tdv = *(const float2*)(time_decay + h0);
    float td[2] = { -__expf(tdv.x) * L2E, -__expf(tdv.y) * L2E };

    const size_t base2 =
        ((size_t)b * S_ * H_ + (size_t)c * CLEN * H_ + (size_t)h0) >> 1;
    const float2* __restrict__ kp = (const float2*)k + base2;
    const float2* __restrict__ vp = (const float2*)v + base2;

    // ---------------- Phase 1: load tile + local scan from identity ----------
    float am[2], an[2], ad[2];
#pragma unroll
    for (int j = 0; j < 2; ++j) { am[j] = -CUDART_INF_F; an[j] = 0.f; ad[j] = 0.f; }

    float2 kb[PF], vb[PF];
#pragma unroll
    for (int r = 0; r < PF; ++r) { kb[r] = __ldcs(kp + r * ROW2); vb[r] = __ldcs(vp + r * ROW2); }

#pragma unroll
    for (int r = 0; r < CLEN; ++r) {
        const int slot = r & (PF - 1);
        float2 k2 = kb[slot];
        const float2 v2 = vb[slot];
        if (r + PF < CLEN) {
            kb[slot] = __ldcs(kp + (r + PF) * ROW2);
            vb[slot] = __ldcs(vp + (r + PF) * ROW2);
        }
        k2.x *= L2E; k2.y *= L2E;
        ks[r * NT + tid] = k2;
        vs[r * NT + tid] = v2;
        const float* kf = (const float*)&k2;
        const float* vf = (const float*)&v2;
#pragma unroll
        for (int j = 0; j < 2; ++j) {
            const float a  = am[j] + td[j];
            const float d2 = a - kf[j];
            const float es = ex2(-fabsf(d2));
            const float e1 = (d2 >= 0.f) ? 1.f : es;
            const float e2 = (d2 >= 0.f) ? es : 1.f;
            am[j] = fmaxf(a, kf[j]);
            an[j] = fmaf(e1, an[j], e2 * vf[j]);
            ad[j] = fmaf(e1, ad[j], e2);
        }
    }

    // ---------------- Phase 2: publish + lookback -> entry state -------------
    const int gi = g * CC + c;
    const int qi = gi * NT + tid;
    float exm[2], exn[2], exd[2];

    if (c == 0) {
        const float2 mm = *(const float2*)(m0 + ch0);
        const float2 nn = *(const float2*)(n0 + ch0);
        const float2 dd = *(const float2*)(d0 + ch0);
        exm[0] = mm.x * L2E; exm[1] = mm.y * L2E;
        exn[0] = nn.x; exn[1] = nn.y;
        exd[0] = dd.x; exd[1] = dd.y;
    } else {
        g_aggm[qi] = make_float2(am[0], am[1]);
        g_aggn[qi] = make_float2(an[0], an[1]);
        g_aggd[qi] = make_float2(ad[0], ad[1]);
        __syncthreads();
        if (tid == 0) st_release(&g_status[gi], 1);

        float sm[2], sn[2], sd[2];
#pragma unroll
        for (int j = 0; j < 2; ++j) { sm[j] = -CUDART_INF_F; sn[j] = 0.f; sd[j] = 0.f; }
        float slen = 0.f;
        int idx = gi - 1;
        int par = 0;

        for (;;) {
            if (tid == 0) {
                int s;
                while ((s = ld_acquire(&g_status[idx])) == 0) __nanosleep(40);
                s_st[par] = s;
            }
            __syncthreads();
            const int s = s_st[par];
            par ^= 1;
            const int q2 = idx * NT + tid;
            if (s == 1) {
                const float2 A_m = g_aggm[q2];
                const float2 A_n = g_aggn[q2];
                const float2 A_d = g_aggd[q2];
                const float* Amf = (const float*)&A_m;
                const float* Anf = (const float*)&A_n;
                const float* Adf = (const float*)&A_d;
#pragma unroll
                for (int j = 0; j < 2; ++j) {
                    const float a  = fmaf(slen, td[j], Amf[j]);
                    const float mo = fmaxf(a, sm[j]);
                    const float e1 = ex2(a - mo);
                    const float e2 = ex2(sm[j] - mo);
                    sn[j] = fmaf(e1, Anf[j], e2 * sn[j]);
                    sd[j] = fmaf(e1, Adf[j], e2 * sd[j]);
                    sm[j] = mo;
                }
                slen += (float)CLEN;
                --idx;
            } else {
                const float2 E_m = g_incm[q2];
                const float2 E_n = g_incn[q2];
                const float2 E_d = g_incd[q2];
                const float* Emf = (const float*)&E_m;
                const float* Enf = (const float*)&E_n;
                const float* Edf = (const float*)&E_d;
#pragma unroll
                for (int j = 0; j < 2; ++j) {
                    const float a  = fmaf(slen, td[j], Emf[j]);
                    const float mo = fmaxf(a, sm[j]);
                    const float e1 = ex2(a - mo);
                    const float e2 = ex2(sm[j] - mo);
                    exn[j] = fmaf(e1, Enf[j], e2 * sn[j]);
                    exd[j] = fmaf(e1, Edf[j], e2 * sd[j]);
                    exm[j] = mo;
                }
                break;
            }
        }
    }

    // inclusive(c) = compose(exclusive, own aggregate over CLEN steps)
    if (c < CC - 1) {
        float im[2], in_[2], id_[2];
#pragma unroll
        for (int j = 0; j < 2; ++j) {
            const float a  = fmaf((float)CLEN, td[j], exm[j]);
            const float mo = fmaxf(a, am[j]);
            const float e1 = ex2(a - mo);
            const float e2 = ex2(am[j] - mo);
            in_[j] = fmaf(e1, exn[j], e2 * an[j]);
            id_[j] = fmaf(e1, exd[j], e2 * ad[j]);
            im[j]  = mo;
        }
        g_incm[qi] = make_float2(im[0], im[1]);
        g_incn[qi] = make_float2(in_[0], in_[1]);
        g_incd[qi] = make_float2(id_[0], id_[1]);
        __syncthreads();
        if (tid == 0) st_release(&g_status[gi], 2);
    }

    // ---------------- Phase 3: outputs from exact entry state (SMEM replay) --
    const float2 tfv = *(const float2*)(time_first + h0);
    float tf[2] = { tfv.x * L2E, tfv.y * L2E };

    float m[2], num[2], den[2];
#pragma unroll
    for (int j = 0; j < 2; ++j) { m[j] = exm[j]; num[j] = exn[j]; den[j] = exd[j]; }

    float2* __restrict__ op = (float2*)out + base2;

#pragma unroll
    for (int r = 0; r < CLEN; ++r) {
        const float2 k2 = ks[r * NT + tid];   // pre-scaled by L2E
        const float2 v2 = vs[r * NT + tid];
        const float* kf = (const float*)&k2;
        const float* vf = (const float*)&v2;
        float2 o2;
        float* of = (float*)&o2;
#pragma unroll
        for (int j = 0; j < 2; ++j) {
            const float kt = kf[j];
            const float vt = vf[j];

            // output branch
            const float btf = kt + tf[j];
            const float d1  = m[j] - btf;
            const float eo  = ex2(-fabsf(d1));
            const float e1o = (d1 >= 0.f) ? 1.f : eo;
            const float e2o = (d1 >= 0.f) ? eo : 1.f;
            const float on  = fmaf(e1o, num[j], e2o * vt);
            const float od  = fmaf(e1o, den[j], e2o);
            of[j] = __fdividef(on, od);

            // state branch
            const float a  = m[j] + td[j];
            const float d2 = a - kt;
            const float es = ex2(-fabsf(d2));
            const float e1 = (d2 >= 0.f) ? 1.f : es;
            const float e2 = (d2 >= 0.f) ? es : 1.f;
            m[j]   = fmaxf(a, kt);
            num[j] = fmaf(e1, num[j], e2 * vt);
            den[j] = fmaf(e1, den[j], e2);
        }
        __stcs(op + r * ROW2, o2);
    }

    if (c == CC - 1) {
        float* st = out + (size_t)B_ * S_ * H_;
        *(float2*)(st + ch0)           = make_float2(m[0] * (1.f / L2E), m[1] * (1.f / L2E));
        *(float2*)(st + BH_ + ch0)     = make_float2(num[0], num[1]);
        *(float2*)(st + 2 * BH_ + ch0) = make_float2(den[0], den[1]);
    }
}

extern "C" void kernel_launch(void* const* d_in, const int* in_sizes, int n_in,
                              void* d_out, int out_size) {
    const float* time_decay = (const float*)d_in[0];
    const float* key        = (const float*)d_in[1];
    const float* time_first = (const float*)d_in[2];
    const float* value      = (const float*)d_in[3];
    const float* max_state  = (const float*)d_in[4];
    const float* num_state  = (const float*)d_in[5];
    const float* den_state  = (const float*)d_in[6];
    float* out = (float*)d_out;

    // Reset status flags via a memset node (replaces the reset kernel launch).
    void* status_ptr = nullptr;
    cudaGetSymbolAddress(&status_ptr, g_status);
    cudaMemsetAsync(status_ptr, 0, GROUPS * CC * sizeof(int), 0);

    const int smem = 2 * CLEN * NT * sizeof(float2);   // 64 KB
    cudaFuncSetAttribute(wkv_main, cudaFuncAttributeMaxDynamicSharedMemorySize, smem);

    wkv_main<<<GROUPS * CC, NT, smem>>>(time_decay, key, time_first, value,
                                        max_state, num_state, den_state, out);
}